// round 14
// baseline (speedup 1.0000x reference)
#include <cuda_runtime.h>
#include <cuda_bf16.h>

// ODE-GRU: B=128, L=2048, I=D=64.
// Round 14 (R13 fixed): 3 serial phases/step. Uses the validated identity
//   gh = (h*w_hh^T + b_hh) + dt*(M*t1 + c),  M = w_hh@dw2, c = w_hh@db2
// so hode's GEMV leaves the critical path. gx is computed for step t+1
// inside phase C (gates run concurrently on w0,w1). 1 CTA/batch, 256 thr:
//   A: t1 (w0,w1)              || G1 = h*w_hh^T+b_hh (w2-w7)
//   B: f  (w0,w1, reg-kept)    || G2 = t1*M^T+c (w2-w7); x/dt commit (w2,w3)
//   C: gates (w0,w1)           || gx[t+1] = x*w_ih^T+b_ih (w2-w7)
// w2-w7 hold 3 packed rowsets (192 regs, <255 cap). h and f live in gate-
// thread registers (no smem roundtrip). tanh.approx t1; precise gates.

#define NB 128
#define NL 2048
#define ND 64
#define NG 192

typedef unsigned long long u64;

__device__ float g_M[NG * ND];
__device__ float g_c[NG];

__device__ __forceinline__ u64 fma2(u64 a, u64 b, u64 c) {
    u64 d;
    asm("fma.rn.f32x2 %0, %1, %2, %3;" : "=l"(d) : "l"(a), "l"(b), "l"(c));
    return d;
}
__device__ __forceinline__ u64 add2(u64 a, u64 b) {
    u64 d;
    asm("add.rn.f32x2 %0, %1, %2;" : "=l"(d) : "l"(a), "l"(b));
    return d;
}
__device__ __forceinline__ u64 pk(float lo, float hi) {
    u64 r;
    asm("mov.b64 %0, {%1, %2};" : "=l"(r) : "f"(lo), "f"(hi));
    return r;
}

// dot(w_row[64], v[64]) + bias, w pre-packed f32x2 (bias seeded in acc).
__device__ __forceinline__ float dot64p(const u64* __restrict__ w,
                                        const float* __restrict__ v,
                                        float bias)
{
    const ulonglong2* __restrict__ v2 = (const ulonglong2*)v;
    u64 a0 = pk(bias, 0.f), a1 = 0ull, a2 = 0ull, a3 = 0ull;
#pragma unroll
    for (int q = 0; q < 8; q++) {
        ulonglong2 p = v2[2*q];
        ulonglong2 r = v2[2*q + 1];
        a0 = fma2(w[4*q+0], p.x, a0);
        a1 = fma2(w[4*q+1], p.y, a1);
        a2 = fma2(w[4*q+2], r.x, a2);
        a3 = fma2(w[4*q+3], r.y, a3);
    }
    u64 s = add2(add2(a0, a1), add2(a2, a3));
    return __uint_as_float((unsigned)s) + __uint_as_float((unsigned)(s >> 32));
}

__device__ __forceinline__ float sigmoidf_(float a) {      // precise (gates)
    return __fdividef(1.f, 1.f + __expf(-a));
}
__device__ __forceinline__ float tanhf_fast(float x) {     // precise (n-gate)
    float e = __expf(2.f * x);
    return 1.f - __fdividef(2.f, e + 1.f);
}
__device__ __forceinline__ float tanh_ap(float x) {        // approx (t1 only)
    float y;
    asm("tanh.approx.f32 %0, %1;" : "=f"(y) : "f"(x));
    return y;
}

// ---------------- setup: M = w_hh @ dw2 (192x64), c = w_hh @ db2 -----------
__global__ __launch_bounds__(64)
void setup_Mc_kernel(const float* __restrict__ w_hh,
                     const float* __restrict__ dw2,
                     const float* __restrict__ db2)
{
    const int k = blockIdx.x;    // 0..191
    const int j = threadIdx.x;   // 0..63
    __shared__ float row[ND];
    row[j] = w_hh[k * ND + j];
    __syncthreads();
    float acc = 0.f;
#pragma unroll 8
    for (int i = 0; i < ND; i++) acc = fmaf(row[i], dw2[i * ND + j], acc);
    g_M[k * ND + j] = acc;
    if (j == 0) {
        float c = 0.f;
        for (int i = 0; i < ND; i++) c = fmaf(row[i], db2[i], c);
        g_c[k] = c;
    }
}

// ---------------- recurrent kernel -----------------------------------------
__global__ __launch_bounds__(256, 1)
void odegru_kernel(const float* __restrict__ x,
                   const float* __restrict__ tdel,
                   const int*   __restrict__ seq,
                   const float* __restrict__ h0,
                   const float* __restrict__ w_ih,
                   const float* __restrict__ w_hh,
                   const float* __restrict__ b_ih,
                   const float* __restrict__ b_hh,
                   const float* __restrict__ dw1,
                   const float* __restrict__ db1,
                   const float* __restrict__ dw2,
                   const float* __restrict__ db2,
                   float* __restrict__ out)
{
    const int b   = blockIdx.x;
    const int tid = threadIdx.x;

    __shared__ __align__(16) float sh_h[ND];
    __shared__ __align__(16) float sh_t1[ND];
    __shared__ __align__(16) float sh_G1[NG];     // h*w_hh^T + b_hh
    __shared__ __align__(16) float sh_G2[NG];     // t1*M^T + c
    __shared__ __align__(16) float sh_gx[2][NG];  // double-buffered by parity
    __shared__ __align__(16) float sh_x[2][ND];
    __shared__ float sh_dt[2];

    // ---- packed weight rowsets ----
    // w0,w1 (tid<64):  wA = dw1 row j (db1)    wB = dw2 row j (db2)
    // w2-w7 (tid>=64): wA = w_hh row k (b_hh)  wB = M row k (c)
    //                  wC = w_ih row k (b_ih)
    u64 wA[32], wB[32], wC[32];
    float bA, bB, bC = 0.f;
    if (tid < 64) {
        const u64* pA = (const u64*)(dw1 + tid * ND);
        const u64* pB = (const u64*)(dw2 + tid * ND);
        bA = db1[tid];  bB = db2[tid];
#pragma unroll
        for (int k = 0; k < 32; k++) { wA[k] = pA[k]; wB[k] = pB[k]; }
    } else {
        const int k2 = tid - 64;
        const u64* pA = (const u64*)(w_hh + k2 * ND);
        const u64* pB = (const u64*)(g_M + k2 * ND);
        const u64* pC = (const u64*)(w_ih + k2 * ND);
        bA = b_hh[k2];  bB = g_c[k2];  bC = b_ih[k2];
#pragma unroll
        for (int k = 0; k < 32; k++) { wA[k] = pA[k]; wB[k] = pB[k]; wC[k] = pC[k]; }
    }

    const int sl = seq[b];
    const float* xb  = x + (size_t)b * NL * ND;
    const float* dtb = tdel + (size_t)b * NL;
    float* outb      = out + (size_t)b * NL * ND;

    float hreg = 0.f, fin = 0.f;
    if (tid < 64) {
        hreg = h0[tid];
        sh_h[tid] = hreg;
    }
    float xA = 0.f, dtA = 0.f;                  // prefetch regs (w2,w3 own)
    if (tid >= 64 && tid < 128) {
        const int k2 = tid - 64;
        sh_x[0][k2] = xb[k2];                   // t=0 always live (sl >= 1)
        xA = xb[ND + k2];                       // x for t=1
        if (tid == 64) { sh_dt[0] = dtb[0]; dtA = dtb[1]; }
    }
    __syncthreads();

    // prologue: gx for t=0 (in-loop, phase C of t-1 produces it)
    if (tid >= 64)
        sh_gx[0][tid - 64] = dot64p(wC, sh_x[0], bC);
    __syncthreads();

    for (int t = 0; t < NL; t++) {
        const int cur = t & 1, nxt = cur ^ 1;
        const int tn  = t + 1;

        if (tid < 64) {                        // ---- gate warps w0,w1 ----
            const int j = tid;
            // A: preload gx/dt (final since C(t-1)/B(t-1)); t1 dot
            float gx0 = sh_gx[cur][j];
            float gx1 = sh_gx[cur][64 + j];
            float gx2 = sh_gx[cur][128 + j];
            float dt  = sh_dt[cur];
            sh_t1[j] = tanh_ap(dot64p(wA, sh_h, bA));
            __syncthreads();                   // syncA

            // B: f kept in register; preload G1 (final since syncA)
            float f    = dot64p(wB, sh_t1, bB);
            float G1_0 = sh_G1[j];
            float G1_1 = sh_G1[64 + j];
            float G1_2 = sh_G1[128 + j];
            __syncthreads();                   // syncB

            // C: gates (h and f never touch smem)
            float ho = fmaf(dt, f, hreg);
            float g0 = fmaf(dt, sh_G2[j],       G1_0);
            float g1 = fmaf(dt, sh_G2[64 + j],  G1_1);
            float g2 = fmaf(dt, sh_G2[128 + j], G1_2);
            float r  = sigmoidf_(gx0 + g0);
            float z  = sigmoidf_(gx1 + g1);
            float n  = tanhf_fast(fmaf(r, g2, gx2));
            float hn = fmaf(z, ho - n, n);     // (1-z)*n + z*ho
            hreg = hn;
            sh_h[j] = hn;
            outb[(size_t)t * ND + j] = hn;
            if (t == sl - 1) fin = hn;
            __syncthreads();                   // syncC
        } else if (tid < 128) {                // ---- w2,w3 (+ prefetch) ----
            const int k2 = tid - 64;
            // A: G1 rows 0..63
            sh_G1[k2] = dot64p(wA, sh_h, bA);
            __syncthreads();                   // syncA
            // B: G2 rows 0..63; commit x/dt for t+1; LDG for t+2
            sh_G2[k2] = dot64p(wB, sh_t1, bB);
            sh_x[nxt][k2] = (tn < sl) ? xA : 0.f;   // PaddedBatch mask
            if (tid == 64) sh_dt[nxt] = (tn < sl) ? dtA : 0.f;
            if (t + 2 < NL) {
                xA = xb[(size_t)(t + 2) * ND + k2];
                if (tid == 64) dtA = dtb[t + 2];
            }
            __syncthreads();                   // syncB
            // C: gx rows 0..63 for step t+1 (x[t+1] committed in B)
            if (tn < NL)
                sh_gx[nxt][k2] = dot64p(wC, sh_x[nxt], bC);
            __syncthreads();                   // syncC
        } else {                               // ---- w4-w7 ----
            const int k2 = tid - 64;
            // A: G1 rows 64..191
            sh_G1[k2] = dot64p(wA, sh_h, bA);
            __syncthreads();                   // syncA
            // B: G2 rows 64..191
            sh_G2[k2] = dot64p(wB, sh_t1, bB);
            __syncthreads();                   // syncB
            // C: gx rows 64..191 for step t+1
            if (tn < NL)
                sh_gx[nxt][k2] = dot64p(wC, sh_x[nxt], bC);
            __syncthreads();                   // syncC
        }
    }

    // final hidden state -> second output tensor (1, B, D)
    if (tid < 64)
        out[(size_t)NB * NL * ND + (size_t)b * ND + tid] = fin;
}

extern "C" void kernel_launch(void* const* d_in, const int* in_sizes, int n_in,
                              void* d_out, int out_size)
{
    const float* x    = (const float*)d_in[0];
    const float* tdel = (const float*)d_in[1];
    const int*   seq  = (const int*)  d_in[2];
    const float* h0   = (const float*)d_in[3];
    const float* w_ih = (const float*)d_in[4];
    const float* w_hh = (const float*)d_in[5];
    const float* b_ih = (const float*)d_in[6];
    const float* b_hh = (const float*)d_in[7];
    const float* dw1  = (const float*)d_in[8];
    const float* db1  = (const float*)d_in[9];
    const float* dw2  = (const float*)d_in[10];
    const float* db2  = (const float*)d_in[11];

    setup_Mc_kernel<<<NG, 64>>>(w_hh, dw2, db2);
    odegru_kernel<<<NB, 256>>>(x, tdel, seq, h0, w_ih, w_hh, b_ih, b_hh,
                               dw1, db1, dw2, db2, (float*)d_out);
}